// round 11
// baseline (speedup 1.0000x reference)
#include <cuda_runtime.h>
#include <math.h>

#define NTOK 16384
#define DIM  256
#define NLVL 8
#define NCODE 512

// ---------------- scratch (device globals; no allocation allowed) ----------------
__device__ float g_gsum[DIM];            // running global_sum
__device__ float g_w2[NLVL * NCODE];     // ||W_lk||^2
__device__ float g_kl[NTOK];             // accumulated KL*0.1 per token
__device__ int   g_idx[NLVL * NTOK];     // chosen code per (level, token)
__device__ int   g_cnt[NLVL * NCODE];    // per-level code histogram

// ---------------- f32x2 helpers ----------------
__device__ __forceinline__ unsigned long long ffma2(unsigned long long a,
                                                    unsigned long long b,
                                                    unsigned long long c) {
    unsigned long long d;
    asm("fma.rn.f32x2 %0, %1, %2, %3;" : "=l"(d) : "l"(a), "l"(b), "l"(c));
    return d;
}
__device__ __forceinline__ unsigned long long pack2(float x) {
    unsigned u = __float_as_uint(x);
    unsigned long long r;
    asm("mov.b64 %0, {%1, %1};" : "=l"(r) : "r"(u));
    return r;
}
__device__ __forceinline__ void unpack2(unsigned long long v, float& lo, float& hi) {
    unsigned a, b;
    asm("mov.b64 {%0, %1}, %2;" : "=r"(a), "=r"(b) : "l"(v));
    lo = __uint_as_float(a); hi = __uint_as_float(b);
}

// ---------------- init: zero scratch + ||W||^2 ----------------
__global__ void init_kernel(const float* __restrict__ W) {
    const int tid  = threadIdx.x;
    const int gtid = blockIdx.x * 256 + tid;          // grid 64 x 256 = 16384
    if (blockIdx.x == 0 && tid < DIM) g_gsum[tid] = 0.0f;
    if (blockIdx.x < 16) {
        int i = blockIdx.x * 256 + tid;               // 4096 counters
        g_cnt[i] = 0;
    }
    g_kl[gtid] = 0.0f;
    const int w    = gtid >> 5;                       // 512 warps
    const int lane = gtid & 31;
    for (int row = w; row < NLVL * NCODE; row += 512) {
        const float* p = W + (size_t)row * DIM;
        float s = 0.0f;
        #pragma unroll
        for (int i = 0; i < 8; i++) { float v = p[lane + 32 * i]; s += v * v; }
        #pragma unroll
        for (int off = 16; off; off >>= 1) s += __shfl_xor_sync(0xffffffffu, s, off);
        if (lane == 0) g_w2[row] = s;
    }
}

// ---------------- per-level kernel ----------------
// grid 128 x 256 thr. block = 128 tokens x 512 codes (8 chunks of 64).
// thread (r = tid>>4, c = tid&15): tokens [8r,8r+8), codes [4c,4c+4) of chunk.
// smem floats: sZ 32768 | sW 16384 | sw2 512 | shist 512 | sr2 128 => 201216 B
__global__ __launch_bounds__(256, 1)
void level_kernel(const float* __restrict__ zf, const float* __restrict__ Wl, int l) {
    extern __shared__ float sm[];
    float* sZ   = sm;                 // [d][128] swizzled
    float* sW   = sm + 32768;         // [d][64]  swizzled
    float* sw2  = sm + 49152;         // [512]
    int*  shist = (int*)(sm + 49664); // [512]
    float* sr2  = sm + 50176;         // [128] per-token ||resid||^2

    const int tid = threadIdx.x;
    const int r   = tid >> 4;
    const int c   = tid & 15;
    const int t0  = blockIdx.x * 128;

    for (int i = tid; i < NCODE; i += 256) { sw2[i] = g_w2[l * NCODE + i]; shist[i] = 0; }

    // load resid = zf - g, transposed+swizzled: logical sZ[d][t] at slot
    // group pg = (t>>2) ^ (d&31), elem (t&3)
    #pragma unroll 4
    for (int k = 0; k < 32; k++) {
        int i  = tid + k * 256;
        int d4 = i & 63;
        int t  = i >> 6;
        float4 zv = *(const float4*)(zf + (size_t)(t0 + t) * DIM + 4 * d4);
        float4 gv = *(const float4*)(g_gsum + 4 * d4);
        float v0 = zv.x - gv.x, v1 = zv.y - gv.y, v2 = zv.z - gv.z, v3 = zv.w - gv.w;
        int tg = t >> 2, tl = t & 3;
        int d = 4 * d4;
        sZ[(d+0)*128 + (((tg ^ ((d+0)&31))) << 2) + tl] = v0;
        sZ[(d+1)*128 + (((tg ^ ((d+1)&31))) << 2) + tl] = v1;
        sZ[(d+2)*128 + (((tg ^ ((d+2)&31))) << 2) + tl] = v2;
        sZ[(d+3)*128 + (((tg ^ ((d+3)&31))) << 2) + tl] = v3;
    }
    __syncthreads();

    // per-token ||resid||^2, fp32 sequential over d (128 threads, one per token)
    if (tid < 128) {
        const int t = tid;
        const int tg = t >> 2, tl = t & 3;
        float a = 0.0f;
        #pragma unroll 8
        for (int d = 0; d < DIM; d++) {
            float v = sZ[d * 128 + ((tg ^ (d & 31)) << 2) + tl];
            a = __fmaf_rn(v, v, a);
        }
        sr2[t] = a;
    }
    __syncthreads();

    float r2v[8];
    #pragma unroll
    for (int t = 0; t < 8; t++) r2v[t] = sr2[r * 8 + t];

    // running per-token softmax/argmax state (replicated over the 16 c-lanes)
    // SSd: per-lane partial sum of this lane's 32 dist values (double)
    float M[8], SE[8]; int AI[8]; double SSd[8];
    #pragma unroll
    for (int t = 0; t < 8; t++) { M[t] = -1e30f; SE[t] = 0.0f; AI[t] = 0; SSd[t] = 0.0; }

    for (int ch = 0; ch < 8; ch++) {
        __syncthreads();  // protect sW reuse
        // load W chunk transposed+swizzled: logical sW[d][cc] at
        // group pg = (cc>>2) ^ (d&15), elem (cc&3)
        #pragma unroll 4
        for (int k = 0; k < 16; k++) {
            int i  = tid + k * 256;
            int d4 = i & 63;
            int cc = i >> 6;
            float4 wv = *(const float4*)(Wl + (size_t)(ch * 64 + cc) * DIM + 4 * d4);
            int cg = cc >> 2, cl = cc & 3;
            int d = 4 * d4;
            sW[(d+0)*64 + (((cg ^ ((d+0)&15))) << 2) + cl] = wv.x;
            sW[(d+1)*64 + (((cg ^ ((d+1)&15))) << 2) + cl] = wv.y;
            sW[(d+2)*64 + (((cg ^ ((d+2)&15))) << 2) + cl] = wv.z;
            sW[(d+3)*64 + (((cg ^ ((d+3)&15))) << 2) + cl] = wv.w;
        }
        __syncthreads();

        // ---- mainloop: dot products, tokens packed in f32x2 pairs ----
        unsigned long long acc[4][4];
        #pragma unroll
        for (int a = 0; a < 4; a++)
            #pragma unroll
            for (int b = 0; b < 4; b++) acc[a][b] = 0ull;

        #pragma unroll 4
        for (int d = 0; d < DIM; d++) {
            ulonglong2 z0 = *(const ulonglong2*)(sZ + d * 128 + (((2 * r)     ^ (d & 31)) << 2));
            ulonglong2 z1 = *(const ulonglong2*)(sZ + d * 128 + (((2 * r + 1) ^ (d & 31)) << 2));
            float4 wv = *(const float4*)(sW + d * 64 + ((c ^ (d & 15)) << 2));
            float wf[4] = {wv.x, wv.y, wv.z, wv.w};
            #pragma unroll
            for (int cd = 0; cd < 4; cd++) {
                unsigned long long wp = pack2(wf[cd]);
                acc[0][cd] = ffma2(z0.x, wp, acc[0][cd]);
                acc[1][cd] = ffma2(z0.y, wp, acc[1][cd]);
                acc[2][cd] = ffma2(z1.x, wp, acc[2][cd]);
                acc[3][cd] = ffma2(z1.y, wp, acc[3][cd]);
            }
        }

        // ---- chunk epilogue: replicate reference rounding:
        // dist = -( fl( fl(r2 + w2) - 2*dot ) ), fp32 grid quantization included
        const int base = ch * 64 + c * 4;
        #pragma unroll
        for (int tp = 0; tp < 4; tp++) {
            float sA[4], sB[4];
            #pragma unroll
            for (int cd = 0; cd < 4; cd++) {
                float lo, hi; unpack2(acc[tp][cd], lo, hi);
                float w2v = sw2[base + cd];
                float tA = __fadd_rn(r2v[2 * tp + 0], w2v);
                float tB = __fadd_rn(r2v[2 * tp + 1], w2v);
                sA[cd] = -__fsub_rn(tA, 2.0f * lo);
                sB[cd] = -__fsub_rn(tB, 2.0f * hi);
            }
            #pragma unroll
            for (int half = 0; half < 2; half++) {
                float* s = half ? sB : sA;
                int t = 2 * tp + half;
                // accumulate sum(dist) in double (per-lane partial)
                SSd[t] += (double)s[0] + (double)s[1] + (double)s[2] + (double)s[3];
                // local max/argmax (ties -> smallest index)
                float lmax = s[0]; int larg = base;
                #pragma unroll
                for (int cd = 1; cd < 4; cd++)
                    if (s[cd] > lmax) { lmax = s[cd]; larg = base + cd; }
                #pragma unroll
                for (int off = 8; off; off >>= 1) {
                    float ov = __shfl_xor_sync(0xffffffffu, lmax, off);
                    int   oi = __shfl_xor_sync(0xffffffffu, larg, off);
                    if (ov > lmax || (ov == lmax && oi < larg)) { lmax = ov; larg = oi; }
                }
                float lexp = __expf(s[0] - lmax) + __expf(s[1] - lmax)
                           + __expf(s[2] - lmax) + __expf(s[3] - lmax);
                #pragma unroll
                for (int off = 8; off; off >>= 1)
                    lexp += __shfl_xor_sync(0xffffffffu, lexp, off);
                // online merge with running state (strict > keeps earlier index)
                if (lmax > M[t]) {
                    SE[t] = SE[t] * __expf(M[t] - lmax) + lexp;
                    M[t] = lmax; AI[t] = larg;
                } else {
                    SE[t] += lexp * __expf(lmax - M[t]);
                }
            }
        }
    }

    // ---- reduce SSd across the 16 c-lanes ----
    #pragma unroll
    for (int t = 0; t < 8; t++) {
        #pragma unroll
        for (int off = 8; off; off >>= 1)
            SSd[t] += __shfl_xor_sync(0xffffffffu, SSd[t], off);
    }

    // ---- finalize per token ----
    if (c == 0) {
        #pragma unroll
        for (int t = 0; t < 8; t++) {
            int gt = t0 + r * 8 + t;
            // kl = (max + log(sum exp(dist-max))) - mean(dist) - log K, in double
            double lse = (double)M[t] + log((double)SE[t]);
            double kl  = lse - SSd[t] * (1.0 / 512.0) - 6.238324625039508;
            g_kl[gt] += 0.1f * (float)kl;
            g_idx[l * NTOK + gt] = AI[t];
            atomicAdd(&shist[AI[t]], 1);
        }
    }
    __syncthreads();
    for (int i = tid; i < NCODE; i += 256) {
        int v = shist[i];
        if (v) atomicAdd(&g_cnt[l * NCODE + i], v);
    }
}

// ---------------- global_sum update: g += sum_k cnt_k * W_lk ----------------
__global__ void gsum_kernel(const float* __restrict__ Wl, int l) {
    __shared__ float scnt[NCODE];
    const int tid = threadIdx.x;  // grid 2 x 128
    for (int i = tid; i < NCODE; i += 128) scnt[i] = (float)g_cnt[l * NCODE + i];
    __syncthreads();
    const int d = blockIdx.x * 128 + tid;
    float acc = 0.0f;
    for (int k = 0; k < NCODE; k++) {
        float cv = scnt[k];                 // uniform across block -> uniform branch
        if (cv != 0.0f) acc += cv * Wl[(size_t)k * DIM + d];
    }
    g_gsum[d] += acc;
}

// ---------------- q_out + indices ----------------
// grid 512 x 256 thr; 32 tokens per block; qs padded for conflict-free transpose
__global__ __launch_bounds__(256)
void qout_kernel(const float* __restrict__ W, float* __restrict__ out, int osize) {
    __shared__ float qs[32 * 257];
    __shared__ int sidx[32 * 8];
    const int tid = threadIdx.x;
    const int n0  = blockIdx.x * 32;
    for (int i = tid; i < 256; i += 256)
        sidx[i] = g_idx[(i & 7) * NTOK + n0 + (i >> 3)];
    __syncthreads();
    #pragma unroll 2
    for (int t = 0; t < 32; t++) {
        float a = 0.0f;
        #pragma unroll
        for (int l = 0; l < NLVL; l++)
            a += W[((size_t)l * NCODE + sidx[t * 8 + l]) * DIM + tid];
        qs[t * 257 + tid] = a;
    }
    __syncthreads();
    const int b = n0 >> 10, hw0 = n0 & 1023;
    for (int i = tid; i < 32 * 256; i += 256) {
        int d = i >> 5, j = i & 31;
        int o = b * 262144 + d * 1024 + hw0 + j;
        if (o < osize) out[o] = qs[j * 257 + d];
    }
    for (int i = tid; i < 256; i += 256) {
        int o = 4194304 + n0 * 8 + i;
        if (o < osize) out[o] = (float)sidx[i];
    }
}

// ---------------- loss (per batch; deterministic tree reduce) ----------------
__global__ void loss_kernel(float* __restrict__ out, int osize) {
    __shared__ float red[256];
    const int b = blockIdx.x, tid = threadIdx.x;  // grid 16 x 256
    float acc = 0.0f;
    for (int u = 0; u < 4; u++) {
        int n = b * 1024 + u * 256 + tid;
        float nm[NLVL];
        #pragma unroll
        for (int l = 0; l < NLVL; l++)
            nm[l] = sqrtf(g_w2[l * NCODE + g_idx[l * NTOK + n]]);
        float nl = 0.0f;
        #pragma unroll
        for (int l = 0; l < NLVL - 1; l++) {
            float m = fmaxf(nm[l + 1] / nm[l] * 4.0f, 1.0f) - 1.0f;
            nl += m * m;
        }
        acc += g_kl[n] + 0.1f * (nl * (1.0f / 7.0f));
    }
    red[tid] = acc; __syncthreads();
    for (int s = 128; s; s >>= 1) { if (tid < s) red[tid] += red[tid + s]; __syncthreads(); }
    if (tid == 0) {
        int o = 4194304 + 131072 + b;
        if (o < osize) out[o] = red[0] * (1.0f / 1024.0f);
    }
}

// ---------------- one-hot probs [N, L, K] ----------------
__global__ void probs_kernel(float* __restrict__ out, int osize) {
    long i = (long)blockIdx.x * 256 + threadIdx.x;   // grid 65536 x 256, float4 idx
    long e = i * 4;
    int n  = (int)(e >> 12);
    int l  = ((int)(e >> 9)) & 7;
    int k0 = (int)(e & 511);
    int idx = g_idx[l * NTOK + n];
    float4 v = make_float4(0.f, 0.f, 0.f, 0.f);
    int d = idx - k0;
    if (d == 0) v.x = 1.f; else if (d == 1) v.y = 1.f;
    else if (d == 2) v.z = 1.f; else if (d == 3) v.w = 1.f;
    long o = 4325392 + e;
    if (o + 4 <= (long)osize) *(float4*)(out + o) = v;
}

// ---------------- launch ----------------
extern "C" void kernel_launch(void* const* d_in, const int* in_sizes, int n_in,
                              void* d_out, int out_size) {
    const float* z = (const float*)d_in[0];   // [16384, 256]
    const float* W = (const float*)d_in[1];   // [8, 512, 256]
    float* out = (float*)d_out;

    cudaFuncSetAttribute(level_kernel, cudaFuncAttributeMaxDynamicSharedMemorySize, 201216);

    init_kernel<<<64, 256>>>(W);
    for (int l = 0; l < NLVL; l++) {
        const float* Wl = W + (size_t)l * NCODE * DIM;
        level_kernel<<<128, 256, 201216>>>(z, Wl, l);
        gsum_kernel<<<2, 128>>>(Wl, l);
    }
    qout_kernel<<<512, 256>>>(W, out, out_size);
    loss_kernel<<<16, 256>>>(out, out_size);
    probs_kernel<<<65536, 256>>>(out, out_size);
}

// round 12
// speedup vs baseline: 1.0122x; 1.0122x over previous
#include <cuda_runtime.h>
#include <math.h>

#define NTOK 16384
#define DIM  256
#define NLVL 8
#define NCODE 512

// ---------------- scratch (device globals; no allocation allowed) ----------------
__device__ float g_gsum[DIM];            // running global_sum
__device__ float g_w2[NLVL * NCODE];     // ||W_lk||^2
__device__ float g_kl[NTOK];             // accumulated KL*0.1 per token
__device__ int   g_idx[NLVL * NTOK];     // chosen code per (level, token)
__device__ int   g_cnt[NLVL * NCODE];    // per-level code histogram

// ---------------- f32x2 helpers ----------------
__device__ __forceinline__ unsigned long long ffma2(unsigned long long a,
                                                    unsigned long long b,
                                                    unsigned long long c) {
    unsigned long long d;
    asm("fma.rn.f32x2 %0, %1, %2, %3;" : "=l"(d) : "l"(a), "l"(b), "l"(c));
    return d;
}
__device__ __forceinline__ unsigned long long pack2(float x) {
    unsigned u = __float_as_uint(x);
    unsigned long long r;
    asm("mov.b64 %0, {%1, %1};" : "=l"(r) : "r"(u));
    return r;
}
__device__ __forceinline__ void unpack2(unsigned long long v, float& lo, float& hi) {
    unsigned a, b;
    asm("mov.b64 {%0, %1}, %2;" : "=r"(a), "=r"(b) : "l"(v));
    lo = __uint_as_float(a); hi = __uint_as_float(b);
}

// ---------------- init: zero scratch + ||W||^2 ----------------
__global__ void init_kernel(const float* __restrict__ W) {
    const int tid  = threadIdx.x;
    const int gtid = blockIdx.x * 256 + tid;          // grid 64 x 256 = 16384
    if (blockIdx.x == 0 && tid < DIM) g_gsum[tid] = 0.0f;
    if (blockIdx.x < 16) {
        int i = blockIdx.x * 256 + tid;               // 4096 counters
        g_cnt[i] = 0;
    }
    g_kl[gtid] = 0.0f;
    const int w    = gtid >> 5;                       // 512 warps
    const int lane = gtid & 31;
    for (int row = w; row < NLVL * NCODE; row += 512) {
        const float* p = W + (size_t)row * DIM;
        float s = 0.0f;
        #pragma unroll
        for (int i = 0; i < 8; i++) { float v = p[lane + 32 * i]; s += v * v; }
        #pragma unroll
        for (int off = 16; off; off >>= 1) s += __shfl_xor_sync(0xffffffffu, s, off);
        if (lane == 0) g_w2[row] = s;
    }
}

// ---------------- per-level kernel ----------------
// grid 128 x 512 thr. block = 128 tokens x 512 codes (8 chunks of 64).
// thread (r = tid>>4 in 0..31, c = tid&15): tokens [4r,4r+4), codes [4c,4c+4).
// smem floats: sZ 32768 | sW 16384 | sw2 512 | shist 512 | sr2 128 => 201216 B
__global__ __launch_bounds__(512, 1)
void level_kernel(const float* __restrict__ zf, const float* __restrict__ Wl, int l) {
    extern __shared__ float sm[];
    float* sZ   = sm;                 // [d][128] swizzled: token-group (t>>2)^(d&31)
    float* sW   = sm + 32768;         // [d][64]  swizzled: code-group (cc>>2)^(d&15)
    float* sw2  = sm + 49152;         // [512]
    int*  shist = (int*)(sm + 49664); // [512]
    float* sr2  = sm + 50176;         // [128] per-token ||resid||^2

    const int tid = threadIdx.x;
    const int r   = tid >> 4;          // 0..31 (4 tokens each)
    const int c   = tid & 15;          // 0..15 (4 codes each)
    const int r4  = r << 2;
    const int c4  = c << 2;
    const int t0  = blockIdx.x * 128;

    if (tid < NCODE) { sw2[tid] = g_w2[l * NCODE + tid]; shist[tid] = 0; }

    // load resid = zf - g, transposed+swizzled
    #pragma unroll 4
    for (int k = 0; k < 16; k++) {
        int i  = tid + k * 512;
        int d4 = i & 63;
        int t  = i >> 6;
        float4 zv = *(const float4*)(zf + (size_t)(t0 + t) * DIM + 4 * d4);
        float4 gv = *(const float4*)(g_gsum + 4 * d4);
        float v0 = zv.x - gv.x, v1 = zv.y - gv.y, v2 = zv.z - gv.z, v3 = zv.w - gv.w;
        int tg = t >> 2, tl = t & 3;
        int d = 4 * d4;
        sZ[(d+0)*128 + (((tg ^ ((d+0)&31))) << 2) + tl] = v0;
        sZ[(d+1)*128 + (((tg ^ ((d+1)&31))) << 2) + tl] = v1;
        sZ[(d+2)*128 + (((tg ^ ((d+2)&31))) << 2) + tl] = v2;
        sZ[(d+3)*128 + (((tg ^ ((d+3)&31))) << 2) + tl] = v3;
    }
    __syncthreads();

    // per-token ||resid||^2, fp32 sequential over d (128 threads, one per token)
    if (tid < 128) {
        const int t = tid;
        const int tg = t >> 2, tl = t & 3;
        float a = 0.0f;
        #pragma unroll 8
        for (int d = 0; d < DIM; d++) {
            float v = sZ[d * 128 + ((tg ^ (d & 31)) << 2) + tl];
            a = __fmaf_rn(v, v, a);
        }
        sr2[t] = a;
    }
    __syncthreads();

    float r2v[4];
    #pragma unroll
    for (int t = 0; t < 4; t++) r2v[t] = sr2[r4 + t];

    // running per-token softmax/argmax state (replicated over the 16 c-lanes)
    float M[4], SE[4]; int AI[4]; double SSd[4];
    #pragma unroll
    for (int t = 0; t < 4; t++) { M[t] = -1e30f; SE[t] = 0.0f; AI[t] = 0; SSd[t] = 0.0; }

    for (int ch = 0; ch < 8; ch++) {
        __syncthreads();  // protect sW reuse
        // load W chunk transposed+swizzled
        #pragma unroll 4
        for (int k = 0; k < 8; k++) {
            int i  = tid + k * 512;
            int d4 = i & 63;
            int cc = i >> 6;
            float4 wv = *(const float4*)(Wl + (size_t)(ch * 64 + cc) * DIM + 4 * d4);
            int cg = cc >> 2, cl = cc & 3;
            int d = 4 * d4;
            sW[(d+0)*64 + (((cg ^ ((d+0)&15))) << 2) + cl] = wv.x;
            sW[(d+1)*64 + (((cg ^ ((d+1)&15))) << 2) + cl] = wv.y;
            sW[(d+2)*64 + (((cg ^ ((d+2)&15))) << 2) + cl] = wv.z;
            sW[(d+3)*64 + (((cg ^ ((d+3)&15))) << 2) + cl] = wv.w;
        }
        __syncthreads();

        // ---- mainloop: 4 tokens (2 f32x2 pairs) x 4 codes per thread ----
        unsigned long long acc[2][4];
        #pragma unroll
        for (int a = 0; a < 2; a++)
            #pragma unroll
            for (int b = 0; b < 4; b++) acc[a][b] = 0ull;

        for (int dd = 0; dd < 8; dd++) {
            const float* sZd = sZ + dd * 32 * 128;
            const float* sWd = sW + dd * 32 * 64;
            #pragma unroll
            for (int e = 0; e < 32; e++) {
                // e == d&31; (e&15) == d&15  -> compile-time XOR constants
                ulonglong2 z = *(const ulonglong2*)(sZd + e * 128 + (r4 ^ (e << 2)));
                float4 wv = *(const float4*)(sWd + e * 64 + (c4 ^ ((e & 15) << 2)));
                float wf[4] = {wv.x, wv.y, wv.z, wv.w};
                #pragma unroll
                for (int cd = 0; cd < 4; cd++) {
                    unsigned long long wp = pack2(wf[cd]);
                    acc[0][cd] = ffma2(z.x, wp, acc[0][cd]);
                    acc[1][cd] = ffma2(z.y, wp, acc[1][cd]);
                }
            }
        }

        // ---- chunk epilogue: replicate reference rounding:
        // dist = -( fl( fl(r2 + w2) - 2*dot ) )
        const int base = ch * 64 + c4;
        #pragma unroll
        for (int tp = 0; tp < 2; tp++) {
            float sA[4], sB[4];
            #pragma unroll
            for (int cd = 0; cd < 4; cd++) {
                float lo, hi; unpack2(acc[tp][cd], lo, hi);
                float w2v = sw2[base + cd];
                float tA = __fadd_rn(r2v[2 * tp + 0], w2v);
                float tB = __fadd_rn(r2v[2 * tp + 1], w2v);
                sA[cd] = -__fsub_rn(tA, 2.0f * lo);
                sB[cd] = -__fsub_rn(tB, 2.0f * hi);
            }
            #pragma unroll
            for (int half = 0; half < 2; half++) {
                float* s = half ? sB : sA;
                int t = 2 * tp + half;
                // accumulate sum(dist) in double (per-lane partial)
                SSd[t] += (double)s[0] + (double)s[1] + (double)s[2] + (double)s[3];
                // local max/argmax (ties -> smallest index)
                float lmax = s[0]; int larg = base;
                #pragma unroll
                for (int cd = 1; cd < 4; cd++)
                    if (s[cd] > lmax) { lmax = s[cd]; larg = base + cd; }
                #pragma unroll
                for (int off = 8; off; off >>= 1) {
                    float ov = __shfl_xor_sync(0xffffffffu, lmax, off);
                    int   oi = __shfl_xor_sync(0xffffffffu, larg, off);
                    if (ov > lmax || (ov == lmax && oi < larg)) { lmax = ov; larg = oi; }
                }
                float lexp = __expf(s[0] - lmax) + __expf(s[1] - lmax)
                           + __expf(s[2] - lmax) + __expf(s[3] - lmax);
                #pragma unroll
                for (int off = 8; off; off >>= 1)
                    lexp += __shfl_xor_sync(0xffffffffu, lexp, off);
                // online merge with running state (strict > keeps earlier index)
                if (lmax > M[t]) {
                    SE[t] = SE[t] * __expf(M[t] - lmax) + lexp;
                    M[t] = lmax; AI[t] = larg;
                } else {
                    SE[t] += lexp * __expf(lmax - M[t]);
                }
            }
        }
    }

    // ---- reduce SSd across the 16 c-lanes ----
    #pragma unroll
    for (int t = 0; t < 4; t++) {
        #pragma unroll
        for (int off = 8; off; off >>= 1)
            SSd[t] += __shfl_xor_sync(0xffffffffu, SSd[t], off);
    }

    // ---- finalize per token ----
    if (c == 0) {
        #pragma unroll
        for (int t = 0; t < 4; t++) {
            int gt = t0 + r4 + t;
            // kl = (max + log(sum exp(dist-max))) - mean(dist) - log K, in double
            double lse = (double)M[t] + log((double)SE[t]);
            double kl  = lse - SSd[t] * (1.0 / 512.0) - 6.238324625039508;
            g_kl[gt] += 0.1f * (float)kl;
            g_idx[l * NTOK + gt] = AI[t];
            atomicAdd(&shist[AI[t]], 1);
        }
    }
    __syncthreads();
    if (tid < NCODE) {
        int v = shist[tid];
        if (v) atomicAdd(&g_cnt[l * NCODE + tid], v);
    }
}

// ---------------- global_sum update: g += sum_k cnt_k * W_lk ----------------
__global__ void gsum_kernel(const float* __restrict__ Wl, int l) {
    __shared__ float scnt[NCODE];
    const int tid = threadIdx.x;  // grid 2 x 128
    for (int i = tid; i < NCODE; i += 128) scnt[i] = (float)g_cnt[l * NCODE + i];
    __syncthreads();
    const int d = blockIdx.x * 128 + tid;
    float acc = 0.0f;
    for (int k = 0; k < NCODE; k++) {
        float cv = scnt[k];                 // uniform across block -> uniform branch
        if (cv != 0.0f) acc += cv * Wl[(size_t)k * DIM + d];
    }
    g_gsum[d] += acc;
}

// ---------------- q_out + indices ----------------
// grid 512 x 256 thr; 32 tokens per block; qs padded for conflict-free transpose
__global__ __launch_bounds__(256)
void qout_kernel(const float* __restrict__ W, float* __restrict__ out, int osize) {
    __shared__ float qs[32 * 257];
    __shared__ int sidx[32 * 8];
    const int tid = threadIdx.x;
    const int n0  = blockIdx.x * 32;
    for (int i = tid; i < 256; i += 256)
        sidx[i] = g_idx[(i & 7) * NTOK + n0 + (i >> 3)];
    __syncthreads();
    #pragma unroll 2
    for (int t = 0; t < 32; t++) {
        float a = 0.0f;
        #pragma unroll
        for (int l = 0; l < NLVL; l++)
            a += W[((size_t)l * NCODE + sidx[t * 8 + l]) * DIM + tid];
        qs[t * 257 + tid] = a;
    }
    __syncthreads();
    const int b = n0 >> 10, hw0 = n0 & 1023;
    for (int i = tid; i < 32 * 256; i += 256) {
        int d = i >> 5, j = i & 31;
        int o = b * 262144 + d * 1024 + hw0 + j;
        if (o < osize) out[o] = qs[j * 257 + d];
    }
    for (int i = tid; i < 256; i += 256) {
        int o = 4194304 + n0 * 8 + i;
        if (o < osize) out[o] = (float)sidx[i];
    }
}

// ---------------- loss (per batch; deterministic tree reduce) ----------------
__global__ void loss_kernel(float* __restrict__ out, int osize) {
    __shared__ float red[256];
    const int b = blockIdx.x, tid = threadIdx.x;  // grid 16 x 256
    float acc = 0.0f;
    for (int u = 0; u < 4; u++) {
        int n = b * 1024 + u * 256 + tid;
        float nm[NLVL];
        #pragma unroll
        for (int l = 0; l < NLVL; l++)
            nm[l] = sqrtf(g_w2[l * NCODE + g_idx[l * NTOK + n]]);
        float nl = 0.0f;
        #pragma unroll
        for (int l = 0; l < NLVL - 1; l++) {
            float m = fmaxf(nm[l + 1] / nm[l] * 4.0f, 1.0f) - 1.0f;
            nl += m * m;
        }
        acc += g_kl[n] + 0.1f * (nl * (1.0f / 7.0f));
    }
    red[tid] = acc; __syncthreads();
    for (int s = 128; s; s >>= 1) { if (tid < s) red[tid] += red[tid + s]; __syncthreads(); }
    if (tid == 0) {
        int o = 4194304 + 131072 + b;
        if (o < osize) out[o] = red[0] * (1.0f / 1024.0f);
    }
}

// ---------------- one-hot probs [N, L, K] ----------------
__global__ void probs_kernel(float* __restrict__ out, int osize) {
    long i = (long)blockIdx.x * 256 + threadIdx.x;   // grid 65536 x 256, float4 idx
    long e = i * 4;
    int n  = (int)(e >> 12);
    int l  = ((int)(e >> 9)) & 7;
    int k0 = (int)(e & 511);
    int idx = g_idx[l * NTOK + n];
    float4 v = make_float4(0.f, 0.f, 0.f, 0.f);
    int d = idx - k0;
    if (d == 0) v.x = 1.f; else if (d == 1) v.y = 1.f;
    else if (d == 2) v.z = 1.f; else if (d == 3) v.w = 1.f;
    long o = 4325392 + e;
    if (o + 4 <= (long)osize) *(float4*)(out + o) = v;
}

// ---------------- launch ----------------
extern "C" void kernel_launch(void* const* d_in, const int* in_sizes, int n_in,
                              void* d_out, int out_size) {
    const float* z = (const float*)d_in[0];   // [16384, 256]
    const float* W = (const float*)d_in[1];   // [8, 512, 256]
    float* out = (float*)d_out;

    cudaFuncSetAttribute(level_kernel, cudaFuncAttributeMaxDynamicSharedMemorySize, 201216);

    init_kernel<<<64, 256>>>(W);
    for (int l = 0; l < NLVL; l++) {
        const float* Wl = W + (size_t)l * NCODE * DIM;
        level_kernel<<<128, 512, 201216>>>(z, Wl, l);
        gsum_kernel<<<2, 128>>>(Wl, l);
    }
    qout_kernel<<<512, 256>>>(W, out, out_size);
    loss_kernel<<<16, 256>>>(out, out_size);
    probs_kernel<<<65536, 256>>>(out, out_size);
}